// round 9
// baseline (speedup 1.0000x reference)
#include <cuda_runtime.h>
#include <cuda_fp16.h>
#include <math.h>

#define NN    50000
#define EE    800000
#define FIN   15
#define H1DIM 256           // heads(4) * 64
#define HEADS 4
#define H2DIM 64

// ---------------- scratch (device globals; no allocations allowed) ----------
__device__ __half  g_h1h  [NN * H1DIM];  // layer1 features (fp16)
__device__ __half  g_act1h[NN * H1DIM];  // layer1 activations (fp16, post-ELU)
__device__ float   g_as1  [NN * HEADS];
__device__ float   g_ad1  [NN * HEADS];
__device__ __half  g_h2h  [NN * H2DIM];  // layer2 features (fp16)
__device__ float   g_out2 [NN * H2DIM];  // layer2 normalized output (fp32)
__device__ float   g_as2  [NN];
__device__ float   g_ad2  [NN];
__device__ int     g_cnt  [NN];          // degree counts (real edges only)
__device__ int     g_ptr  [NN + 1];      // CSR row pointers
__device__ int     g_cur  [NN];          // scatter cursors
__device__ int     g_csr  [EE];          // src ids grouped by dst
__device__ float   g_wa1s [FIN * HEADS];
__device__ float   g_wa1d [FIN * HEADS];
__device__ float   g_wa2s [H1DIM];
__device__ float   g_wa2d [H1DIM];
__device__ double  g_final[H2DIM];

__device__ __forceinline__ float elu1(float v) { return v > 0.f ? v : expm1f(v); }
__device__ __forceinline__ float lrelu(float v) { return v > 0.f ? v : 0.2f * v; }

// ---------------- kernels ---------------------------------------------------
// fold attention vectors into tiny per-input-dim weights; zero g_final
__global__ void k_pre(const float* __restrict__ W1, const float* __restrict__ as1,
                      const float* __restrict__ ad1, const float* __restrict__ W2,
                      const float* __restrict__ as2, const float* __restrict__ ad2) {
    int t = threadIdx.x;  // 256
    if (t < H2DIM) g_final[t] = 0.0;
    float s = 0.f, d = 0.f;
    for (int j = 0; j < 64; j++) {
        float w = W2[t * 64 + j];
        s = fmaf(w, as2[j], s);
        d = fmaf(w, ad2[j], d);
    }
    g_wa2s[t] = s; g_wa2d[t] = d;
    if (t < FIN * HEADS) {
        int k = t >> 2, h = t & 3;
        float a = 0.f, b = 0.f;
        for (int j = 0; j < 64; j++) {
            float w = W1[k * H1DIM + h * 64 + j];
            a = fmaf(w, as1[h * 64 + j], a);
            b = fmaf(w, ad1[h * 64 + j], b);
        }
        g_wa1s[t] = a; g_wa1d[t] = b;
    }
}

// h1 = x @ W1 (fp16 pair stores), logits, zero degree counts.
#define G1TILE 32
__global__ void __launch_bounds__(256) k_gemm1(const float* __restrict__ x,
                                               const float* __restrict__ W1) {
    __shared__ float sW[FIN * H1DIM];
    __shared__ float sx[G1TILE * 16];
    int t = threadIdx.x;  // 256
    for (int j = t; j < FIN * H1DIM; j += 256) sW[j] = W1[j];
    int base = blockIdx.x * G1TILE;
    for (int j = t; j < G1TILE * FIN; j += 256) {
        int r = j / FIN, k = j - r * FIN;
        int n = base + r;
        sx[r * 16 + k] = (n < NN) ? x[n * FIN + k] : 0.f;
    }
    __syncthreads();
    float wcol[FIN];
#pragma unroll
    for (int k = 0; k < FIN; k++) wcol[k] = sW[k * H1DIM + t];
    int nmax = NN - base;
#pragma unroll 4
    for (int r = 0; r < G1TILE; r++) {
        if (r >= nmax) break;
        int n = base + r;
        float h = 0.f;
#pragma unroll
        for (int k = 0; k < FIN; k++) h = fmaf(sx[r * 16 + k], wcol[k], h);
        float hn = __shfl_down_sync(0xffffffffu, h, 1);
        if (!(t & 1))
            *(__half2*)(g_h1h + (size_t)n * H1DIM + t) = __floats2half2_rn(h, hn);
    }
    if (t < G1TILE && t < nmax) g_cnt[base + t] = 0;
    // logits: 256 threads = 32 nodes x 8 (4 src + 4 dst)
    {
        int r = t >> 3, idx = t & 7, hh = idx & 3;
        if (r < nmax) {
            const float* wa = (idx < 4) ? g_wa1s : g_wa1d;
            float a = 0.f;
#pragma unroll
            for (int k = 0; k < FIN; k++) a = fmaf(sx[r * 16 + k], wa[k * HEADS + hh], a);
            int n = base + r;
            if (idx < 4) g_as1[n * HEADS + hh] = a;
            else         g_ad1[n * HEADS + hh] = a;
        }
    }
}

// ---- CSR build -------------------------------------------------------------
__global__ void k_deg(const int* __restrict__ ei) {
    int i = blockIdx.x * blockDim.x + threadIdx.x;
    if (i < EE) atomicAdd(&g_cnt[ei[EE + i]], 1);
}

// exclusive scan of g_cnt -> g_ptr / g_cur.  One block, 1024 threads.
__global__ void __launch_bounds__(1024) k_scan() {
    int t = threadIdx.x;
    const int C = (NN + 1023) / 1024;  // 49
    int beg = t * C, end = beg + C;
    if (beg > NN) beg = NN;
    if (end > NN) end = NN;
    int s = 0;
    for (int i = beg; i < end; i++) s += g_cnt[i];
    int lane = t & 31, wid = t >> 5;
    int v = s;
#pragma unroll
    for (int o = 1; o < 32; o <<= 1) {
        int u = __shfl_up_sync(0xffffffffu, v, o);
        if (lane >= o) v += u;
    }
    __shared__ int wsum[32];
    if (lane == 31) wsum[wid] = v;
    __syncthreads();
    if (wid == 0) {
        int v2 = wsum[lane];
#pragma unroll
        for (int o = 1; o < 32; o <<= 1) {
            int u = __shfl_up_sync(0xffffffffu, v2, o);
            if (lane >= o) v2 += u;
        }
        wsum[lane] = v2;
    }
    __syncthreads();
    int excl = v - s + (wid > 0 ? wsum[wid - 1] : 0);
    int run = excl;
    for (int i = beg; i < end; i++) {
        int c = g_cnt[i];
        g_ptr[i] = run;
        g_cur[i] = run;
        run += c;
    }
    if (beg < NN && end == NN) g_ptr[NN] = run;
}

__global__ void k_scatter(const int* __restrict__ ei) {
    int i = blockIdx.x * blockDim.x + threadIdx.x;
    if (i >= EE) return;
    int s = ei[i], d = ei[EE + i];
    int pos = atomicAdd(&g_cur[d], 1);
    g_csr[pos] = s;
}

// ---- layer-1 node aggregation: warp per dst node ---------------------------
// softmax weights (no max shift; |logit| is O(5)), fp32 register accum,
// normalize + bias + ELU + layer-2 logits, store act fp16.
__global__ void __launch_bounds__(256) k_node1(const float* __restrict__ b1) {
    int t = threadIdx.x, lane = t & 31, w = t >> 5;
    int n = blockIdx.x * 8 + w;
    if (n >= NN) return;
    int h = lane >> 3;
    float adv = g_ad1[n * HEADS + h];
    int beg = g_ptr[n], end = g_ptr[n + 1];
    // self loop
    float wv = expf(lrelu(g_as1[n * HEADS + h] + adv));
    float z = wv;
    uint4 hv = ((const uint4*)(g_h1h + (size_t)n * H1DIM))[lane];
    float2 f0 = __half22float2(*(__half2*)&hv.x);
    float2 f1 = __half22float2(*(__half2*)&hv.y);
    float2 f2 = __half22float2(*(__half2*)&hv.z);
    float2 f3 = __half22float2(*(__half2*)&hv.w);
    float a0 = wv * f0.x, a1 = wv * f0.y, a2 = wv * f1.x, a3 = wv * f1.y;
    float a4 = wv * f2.x, a5 = wv * f2.y, a6 = wv * f3.x, a7 = wv * f3.y;
    // real edges with 1-deep prefetch
    int   sn = 0; uint4 hn; float en = 0.f;
    if (beg < end) {
        sn = g_csr[beg];
        hn = ((const uint4*)(g_h1h + (size_t)sn * H1DIM))[lane];
        en = g_as1[sn * HEADS + h];
    }
    for (int j = beg; j < end; j++) {
        uint4 hc = hn; float ec = en;
        if (j + 1 < end) {
            int s2 = g_csr[j + 1];
            hn = ((const uint4*)(g_h1h + (size_t)s2 * H1DIM))[lane];
            en = g_as1[s2 * HEADS + h];
        }
        float wj = expf(lrelu(ec + adv));
        z += wj;
        f0 = __half22float2(*(__half2*)&hc.x);
        f1 = __half22float2(*(__half2*)&hc.y);
        f2 = __half22float2(*(__half2*)&hc.z);
        f3 = __half22float2(*(__half2*)&hc.w);
        a0 = fmaf(wj, f0.x, a0); a1 = fmaf(wj, f0.y, a1);
        a2 = fmaf(wj, f1.x, a2); a3 = fmaf(wj, f1.y, a3);
        a4 = fmaf(wj, f2.x, a4); a5 = fmaf(wj, f2.y, a5);
        a6 = fmaf(wj, f3.x, a6); a7 = fmaf(wj, f3.y, a7);
    }
    float rz = 1.f / z;
    float4 b1v0 = __ldg((const float4*)(b1 + 8 * lane));
    float4 b1v1 = __ldg((const float4*)(b1 + 8 * lane + 4));
    a0 = elu1(a0 * rz + b1v0.x); a1 = elu1(a1 * rz + b1v0.y);
    a2 = elu1(a2 * rz + b1v0.z); a3 = elu1(a3 * rz + b1v0.w);
    a4 = elu1(a4 * rz + b1v1.x); a5 = elu1(a5 * rz + b1v1.y);
    a6 = elu1(a6 * rz + b1v1.z); a7 = elu1(a7 * rz + b1v1.w);
    uint4 ov;
    *(__half2*)&ov.x = __floats2half2_rn(a0, a1);
    *(__half2*)&ov.y = __floats2half2_rn(a2, a3);
    *(__half2*)&ov.z = __floats2half2_rn(a4, a5);
    *(__half2*)&ov.w = __floats2half2_rn(a6, a7);
    ((uint4*)(g_act1h + (size_t)n * H1DIM))[lane] = ov;
    // layer-2 logits
    float4 ws0 = __ldg((const float4*)(g_wa2s + 8 * lane));
    float4 ws1 = __ldg((const float4*)(g_wa2s + 8 * lane + 4));
    float4 wd0 = __ldg((const float4*)(g_wa2d + 8 * lane));
    float4 wd1 = __ldg((const float4*)(g_wa2d + 8 * lane + 4));
    float ps = a0 * ws0.x + a1 * ws0.y + a2 * ws0.z + a3 * ws0.w
             + a4 * ws1.x + a5 * ws1.y + a6 * ws1.z + a7 * ws1.w;
    float pd = a0 * wd0.x + a1 * wd0.y + a2 * wd0.z + a3 * wd0.w
             + a4 * wd1.x + a5 * wd1.y + a6 * wd1.z + a7 * wd1.w;
#pragma unroll
    for (int o = 16; o; o >>= 1) {
        ps += __shfl_xor_sync(0xffffffffu, ps, o);
        pd += __shfl_xor_sync(0xffffffffu, pd, o);
    }
    if (lane == 0) {
        g_as2[n] = ps;
        g_ad2[n] = pd;
    }
}

// h2 = act @ W2 (4 nodes x 4 cols / thread), fp16 stores.
#define SA_STRIDE 264
#define TILE 64
__global__ void __launch_bounds__(256) k_l2(const float* __restrict__ W2) {
    __shared__ float sA[TILE * SA_STRIDE];
    int t = threadIdx.x, lane = t & 31, w = t >> 5;
    int base = blockIdx.x * TILE;
    for (int r = w; r < TILE; r += 8) {
        int n = base + r;
        float4 o0 = {0,0,0,0}, o1 = {0,0,0,0};
        if (n < NN) {
            uint4 hv = ((const uint4*)(g_act1h + (size_t)n * H1DIM))[lane];
            float2 f0 = __half22float2(*(__half2*)&hv.x);
            float2 f1 = __half22float2(*(__half2*)&hv.y);
            float2 f2 = __half22float2(*(__half2*)&hv.z);
            float2 f3 = __half22float2(*(__half2*)&hv.w);
            o0.x = f0.x; o0.y = f0.y; o0.z = f1.x; o0.w = f1.y;
            o1.x = f2.x; o1.y = f2.y; o1.z = f3.x; o1.w = f3.y;
        }
        float4* sp = (float4*)(sA + r * SA_STRIDE + 8 * lane);
        sp[0] = o0;
        sp[1] = o1;
    }
    __syncthreads();
    int cg = t & 15;
    int ng = t >> 4;
    const float4* W2v4 = (const float4*)W2;
    float4 acc0 = {0,0,0,0}, acc1 = {0,0,0,0}, acc2 = {0,0,0,0}, acc3 = {0,0,0,0};
    const float* a0 = sA + (ng     ) * SA_STRIDE;
    const float* a1 = sA + (ng + 16) * SA_STRIDE;
    const float* a2 = sA + (ng + 32) * SA_STRIDE;
    const float* a3 = sA + (ng + 48) * SA_STRIDE;
#pragma unroll 4
    for (int k = 0; k < H1DIM; k += 4) {
        float4 v0 = *(const float4*)(a0 + k);
        float4 v1 = *(const float4*)(a1 + k);
        float4 v2 = *(const float4*)(a2 + k);
        float4 v3 = *(const float4*)(a3 + k);
        float4 w0 = __ldg(&W2v4[(k + 0) * 16 + cg]);
        float4 w1 = __ldg(&W2v4[(k + 1) * 16 + cg]);
        float4 w2 = __ldg(&W2v4[(k + 2) * 16 + cg]);
        float4 w3 = __ldg(&W2v4[(k + 3) * 16 + cg]);
#define STEP(vv, ww) \
        acc0.x = fmaf(v0.vv, ww.x, acc0.x); acc0.y = fmaf(v0.vv, ww.y, acc0.y); \
        acc0.z = fmaf(v0.vv, ww.z, acc0.z); acc0.w = fmaf(v0.vv, ww.w, acc0.w); \
        acc1.x = fmaf(v1.vv, ww.x, acc1.x); acc1.y = fmaf(v1.vv, ww.y, acc1.y); \
        acc1.z = fmaf(v1.vv, ww.z, acc1.z); acc1.w = fmaf(v1.vv, ww.w, acc1.w); \
        acc2.x = fmaf(v2.vv, ww.x, acc2.x); acc2.y = fmaf(v2.vv, ww.y, acc2.y); \
        acc2.z = fmaf(v2.vv, ww.z, acc2.z); acc2.w = fmaf(v2.vv, ww.w, acc2.w); \
        acc3.x = fmaf(v3.vv, ww.x, acc3.x); acc3.y = fmaf(v3.vv, ww.y, acc3.y); \
        acc3.z = fmaf(v3.vv, ww.z, acc3.z); acc3.w = fmaf(v3.vv, ww.w, acc3.w);
        STEP(x, w0) STEP(y, w1) STEP(z, w2) STEP(w, w3)
#undef STEP
    }
    float4 accs[4] = {acc0, acc1, acc2, acc3};
#pragma unroll
    for (int i = 0; i < 4; i++) {
        int n = base + ng + 16 * i;
        if (n < NN) {
            __half2* hp = (__half2*)(g_h2h + (size_t)n * H2DIM + 4 * cg);
            float4 v = accs[i];
            hp[0] = __floats2half2_rn(v.x, v.y);
            hp[1] = __floats2half2_rn(v.z, v.w);
        }
    }
}

// ---- layer-2 node aggregation: warp per dst node ---------------------------
__global__ void __launch_bounds__(256) k_node2() {
    int t = threadIdx.x, lane = t & 31, w = t >> 5;
    int n = blockIdx.x * 8 + w;
    if (n >= NN) return;
    float adv = g_ad2[n];
    int beg = g_ptr[n], end = g_ptr[n + 1];
    // self loop
    float wv = expf(lrelu(g_as2[n] + adv));
    float z = wv;
    unsigned hu = ((const unsigned*)(g_h2h + (size_t)n * H2DIM))[lane];
    float2 f = __half22float2(*(__half2*)&hu);
    float ax = wv * f.x, ay = wv * f.y;
    int sn = 0; unsigned hn = 0; float en = 0.f;
    if (beg < end) {
        sn = g_csr[beg];
        hn = ((const unsigned*)(g_h2h + (size_t)sn * H2DIM))[lane];
        en = g_as2[sn];
    }
    for (int j = beg; j < end; j++) {
        unsigned hc = hn; float ec = en;
        if (j + 1 < end) {
            int s2 = g_csr[j + 1];
            hn = ((const unsigned*)(g_h2h + (size_t)s2 * H2DIM))[lane];
            en = g_as2[s2];
        }
        float wj = expf(lrelu(ec + adv));
        z += wj;
        f = __half22float2(*(__half2*)&hc);
        ax = fmaf(wj, f.x, ax);
        ay = fmaf(wj, f.y, ay);
    }
    float rz = 1.f / z;
    float2 o = {ax * rz, ay * rz};
    *(float2*)(g_out2 + (size_t)n * H2DIM + 2 * lane) = o;
}

// mean over nodes (bias folded into k_out)
__global__ void k_final() {
    int t = threadIdx.x;  // 256
    int col = t & 63, ns = t >> 6;
    double sum = 0.0;
    for (int n = blockIdx.x * 4 + ns; n < NN; n += gridDim.x * 4)
        sum += (double)g_out2[(size_t)n * H2DIM + col];
    __shared__ double sd[256];
    sd[t] = sum;
    __syncthreads();
    if (t < 128) sd[t] += sd[t + 128];
    __syncthreads();
    if (t < 64) atomicAdd(&g_final[t], sd[t] + sd[t + 64]);
}

__global__ void k_out(float* __restrict__ out, const float* __restrict__ b2) {
    int t = threadIdx.x;
    if (t < H2DIM) out[t] = (float)(g_final[t] * (1.0 / (double)NN)) + b2[t];
}

// ---------------- launch -----------------------------------------------------
extern "C" void kernel_launch(void* const* d_in, const int* in_sizes, int n_in,
                              void* d_out, int out_size) {
    const float* x   = (const float*)d_in[0];
    const int*   ei  = (const int*)d_in[1];   // jax demotes int64 -> int32
    const float* W1  = (const float*)d_in[2];
    const float* as1 = (const float*)d_in[3];
    const float* ad1 = (const float*)d_in[4];
    const float* b1  = (const float*)d_in[5];
    const float* W2  = (const float*)d_in[6];
    const float* as2 = (const float*)d_in[7];
    const float* ad2 = (const float*)d_in[8];
    const float* b2  = (const float*)d_in[9];
    float* out = (float*)d_out;

    (void)in_sizes; (void)n_in; (void)out_size;

    k_pre<<<1, 256>>>(W1, as1, ad1, W2, as2, ad2);
    k_gemm1<<<(NN + G1TILE - 1) / G1TILE, 256>>>(x, W1);
    k_deg<<<(EE + 255) / 256, 256>>>(ei);
    k_scan<<<1, 1024>>>();
    k_scatter<<<(EE + 255) / 256, 256>>>(ei);
    k_node1<<<(NN + 7) / 8, 256>>>(b1);
    k_l2<<<(NN + TILE - 1) / TILE, 256>>>(W2);
    k_node2<<<(NN + 7) / 8, 256>>>();
    k_final<<<148, 256>>>();
    k_out<<<1, 64>>>(out, b2);
}

// round 11
// speedup vs baseline: 1.2687x; 1.2687x over previous
#include <cuda_runtime.h>
#include <cuda_fp16.h>
#include <math.h>

#define NN    50000
#define EE    800000
#define FIN   15
#define H1DIM 256           // heads(4) * 64
#define HEADS 4
#define H2DIM 64

#define SCB   512                       // scan block size
#define NSCB  ((NN + SCB - 1) / SCB)    // 98 scan blocks

// ---------------- scratch (device globals; no allocations allowed) ----------
__device__ __half  g_h1h  [NN * H1DIM];  // layer1 features (fp16)
__device__ __half  g_act1h[NN * H1DIM];  // layer1 activations (fp16, post-ELU)
__device__ float   g_as1  [NN * HEADS];
__device__ float   g_ad1  [NN * HEADS];
__device__ __half  g_h2h  [NN * H2DIM];  // layer2 features (fp16)
__device__ float   g_out2 [NN * H2DIM];  // layer2 normalized output (fp32)
__device__ float   g_as2  [NN];
__device__ float   g_ad2  [NN];
__device__ int     g_cnt  [NN];          // degree counts (real edges only)
__device__ int     g_ptr  [NN + 1];      // CSR row pointers
__device__ int     g_cur  [NN];          // scatter cursors
__device__ int     g_csr  [EE];          // src ids grouped by dst
__device__ int     g_bsum [NSCB];        // scan block sums
__device__ int     g_boff [NSCB];        // scan block offsets
__device__ float   g_wa1s [FIN * HEADS];
__device__ float   g_wa1d [FIN * HEADS];
__device__ float   g_wa2s [H1DIM];
__device__ float   g_wa2d [H1DIM];
__device__ double  g_final[H2DIM];

__device__ __forceinline__ float elu1(float v) { return v > 0.f ? v : expm1f(v); }
__device__ __forceinline__ float lrelu(float v) { return v > 0.f ? v : 0.2f * v; }

// ---------------- kernels ---------------------------------------------------
// fold attention vectors into tiny per-input-dim weights; zero g_final
__global__ void k_pre(const float* __restrict__ W1, const float* __restrict__ as1,
                      const float* __restrict__ ad1, const float* __restrict__ W2,
                      const float* __restrict__ as2, const float* __restrict__ ad2) {
    int t = threadIdx.x;  // 256
    if (t < H2DIM) g_final[t] = 0.0;
    float s = 0.f, d = 0.f;
    for (int j = 0; j < 64; j++) {
        float w = W2[t * 64 + j];
        s = fmaf(w, as2[j], s);
        d = fmaf(w, ad2[j], d);
    }
    g_wa2s[t] = s; g_wa2d[t] = d;
    if (t < FIN * HEADS) {
        int k = t >> 2, h = t & 3;
        float a = 0.f, b = 0.f;
        for (int j = 0; j < 64; j++) {
            float w = W1[k * H1DIM + h * 64 + j];
            a = fmaf(w, as1[h * 64 + j], a);
            b = fmaf(w, ad1[h * 64 + j], b);
        }
        g_wa1s[t] = a; g_wa1d[t] = b;
    }
}

// h1 = x @ W1 (fp16 pair stores), logits, zero degree counts.
#define G1TILE 32
__global__ void __launch_bounds__(256) k_gemm1(const float* __restrict__ x,
                                               const float* __restrict__ W1) {
    __shared__ float sW[FIN * H1DIM];
    __shared__ float sx[G1TILE * 16];
    int t = threadIdx.x;  // 256
    for (int j = t; j < FIN * H1DIM; j += 256) sW[j] = W1[j];
    int base = blockIdx.x * G1TILE;
    for (int j = t; j < G1TILE * FIN; j += 256) {
        int r = j / FIN, k = j - r * FIN;
        int n = base + r;
        sx[r * 16 + k] = (n < NN) ? x[n * FIN + k] : 0.f;
    }
    __syncthreads();
    float wcol[FIN];
#pragma unroll
    for (int k = 0; k < FIN; k++) wcol[k] = sW[k * H1DIM + t];
    int nmax = NN - base;
#pragma unroll 4
    for (int r = 0; r < G1TILE; r++) {
        if (r >= nmax) break;
        int n = base + r;
        float h = 0.f;
#pragma unroll
        for (int k = 0; k < FIN; k++) h = fmaf(sx[r * 16 + k], wcol[k], h);
        float hn = __shfl_down_sync(0xffffffffu, h, 1);
        if (!(t & 1))
            *(__half2*)(g_h1h + (size_t)n * H1DIM + t) = __floats2half2_rn(h, hn);
    }
    if (t < G1TILE && t < nmax) g_cnt[base + t] = 0;
    // logits: 256 threads = 32 nodes x 8 (4 src + 4 dst)
    {
        int r = t >> 3, idx = t & 7, hh = idx & 3;
        if (r < nmax) {
            const float* wa = (idx < 4) ? g_wa1s : g_wa1d;
            float a = 0.f;
#pragma unroll
            for (int k = 0; k < FIN; k++) a = fmaf(sx[r * 16 + k], wa[k * HEADS + hh], a);
            int n = base + r;
            if (idx < 4) g_as1[n * HEADS + hh] = a;
            else         g_ad1[n * HEADS + hh] = a;
        }
    }
}

// ---- CSR build -------------------------------------------------------------
__global__ void k_deg(const int* __restrict__ ei) {
    int i = blockIdx.x * blockDim.x + threadIdx.x;
    if (i < EE) atomicAdd(&g_cnt[ei[EE + i]], 1);
}

// pass A: per-block sums of 512 counts
__global__ void __launch_bounds__(SCB) k_scanA() {
    int t = threadIdx.x, b = blockIdx.x;
    int i = b * SCB + t;
    int c = (i < NN) ? g_cnt[i] : 0;
    int lane = t & 31, wid = t >> 5;
    int v = c;
#pragma unroll
    for (int o = 16; o; o >>= 1) v += __shfl_xor_sync(0xffffffffu, v, o);
    __shared__ int ws[SCB / 32];
    if (lane == 0) ws[wid] = v;
    __syncthreads();
    if (t == 0) {
        int s = 0;
#pragma unroll
        for (int j = 0; j < SCB / 32; j++) s += ws[j];
        g_bsum[b] = s;
    }
}

// pass B: serial exclusive prefix over NSCB block sums (tiny)
__global__ void k_scanB() {
    if (threadIdx.x == 0) {
        int run = 0;
        for (int j = 0; j < NSCB; j++) {
            g_boff[j] = run;
            run += g_bsum[j];
        }
    }
}

// pass C: block-wide exclusive scan + offset -> g_ptr / g_cur
__global__ void __launch_bounds__(SCB) k_scanC() {
    int t = threadIdx.x, b = blockIdx.x;
    int i = b * SCB + t;
    int c = (i < NN) ? g_cnt[i] : 0;
    int lane = t & 31, wid = t >> 5;
    int v = c;
#pragma unroll
    for (int o = 1; o < 32; o <<= 1) {
        int u = __shfl_up_sync(0xffffffffu, v, o);
        if (lane >= o) v += u;
    }
    __shared__ int ws[32];               // padded to full warp
    if (t < 32) ws[t] = 0;               // zero-fill lanes >= SCB/32
    __syncthreads();
    if (lane == 31) ws[wid] = v;
    __syncthreads();
    if (wid == 0) {                      // ALL 32 lanes participate (fix)
        int v2 = ws[lane];
#pragma unroll
        for (int o = 1; o < 32; o <<= 1) {
            int u = __shfl_up_sync(0xffffffffu, v2, o);
            if (lane >= o) v2 += u;
        }
        ws[lane] = v2;
    }
    __syncthreads();
    int excl = v - c + (wid > 0 ? ws[wid - 1] : 0) + g_boff[b];
    if (i < NN) {
        g_ptr[i] = excl;
        g_cur[i] = excl;
    }
    if (i == NN - 1) g_ptr[NN] = EE;
}

__global__ void k_scatter(const int* __restrict__ ei) {
    int i = blockIdx.x * blockDim.x + threadIdx.x;
    if (i >= EE) return;
    int s = ei[i], d = ei[EE + i];
    int pos = atomicAdd(&g_cur[d], 1);
    g_csr[pos] = s;
}

// ---- layer-1 node aggregation: warp per dst node ---------------------------
__global__ void __launch_bounds__(256) k_node1(const float* __restrict__ b1) {
    int t = threadIdx.x, lane = t & 31, w = t >> 5;
    int n = blockIdx.x * 8 + w;
    if (n >= NN) return;
    int h = lane >> 3;
    float adv = g_ad1[n * HEADS + h];
    int beg = g_ptr[n], end = g_ptr[n + 1];
    // self loop
    float wv = expf(lrelu(g_as1[n * HEADS + h] + adv));
    float z = wv;
    uint4 hv = ((const uint4*)(g_h1h + (size_t)n * H1DIM))[lane];
    float2 f0 = __half22float2(*(__half2*)&hv.x);
    float2 f1 = __half22float2(*(__half2*)&hv.y);
    float2 f2 = __half22float2(*(__half2*)&hv.z);
    float2 f3 = __half22float2(*(__half2*)&hv.w);
    float a0 = wv * f0.x, a1 = wv * f0.y, a2 = wv * f1.x, a3 = wv * f1.y;
    float a4 = wv * f2.x, a5 = wv * f2.y, a6 = wv * f3.x, a7 = wv * f3.y;
    // real edges with 1-deep prefetch
    int   sn = 0; uint4 hn; float en = 0.f;
    if (beg < end) {
        sn = g_csr[beg];
        hn = ((const uint4*)(g_h1h + (size_t)sn * H1DIM))[lane];
        en = g_as1[sn * HEADS + h];
    }
    for (int j = beg; j < end; j++) {
        uint4 hc = hn; float ec = en;
        if (j + 1 < end) {
            int s2 = g_csr[j + 1];
            hn = ((const uint4*)(g_h1h + (size_t)s2 * H1DIM))[lane];
            en = g_as1[s2 * HEADS + h];
        }
        float wj = expf(lrelu(ec + adv));
        z += wj;
        f0 = __half22float2(*(__half2*)&hc.x);
        f1 = __half22float2(*(__half2*)&hc.y);
        f2 = __half22float2(*(__half2*)&hc.z);
        f3 = __half22float2(*(__half2*)&hc.w);
        a0 = fmaf(wj, f0.x, a0); a1 = fmaf(wj, f0.y, a1);
        a2 = fmaf(wj, f1.x, a2); a3 = fmaf(wj, f1.y, a3);
        a4 = fmaf(wj, f2.x, a4); a5 = fmaf(wj, f2.y, a5);
        a6 = fmaf(wj, f3.x, a6); a7 = fmaf(wj, f3.y, a7);
    }
    float rz = 1.f / z;
    float4 b1v0 = __ldg((const float4*)(b1 + 8 * lane));
    float4 b1v1 = __ldg((const float4*)(b1 + 8 * lane + 4));
    a0 = elu1(a0 * rz + b1v0.x); a1 = elu1(a1 * rz + b1v0.y);
    a2 = elu1(a2 * rz + b1v0.z); a3 = elu1(a3 * rz + b1v0.w);
    a4 = elu1(a4 * rz + b1v1.x); a5 = elu1(a5 * rz + b1v1.y);
    a6 = elu1(a6 * rz + b1v1.z); a7 = elu1(a7 * rz + b1v1.w);
    uint4 ov;
    *(__half2*)&ov.x = __floats2half2_rn(a0, a1);
    *(__half2*)&ov.y = __floats2half2_rn(a2, a3);
    *(__half2*)&ov.z = __floats2half2_rn(a4, a5);
    *(__half2*)&ov.w = __floats2half2_rn(a6, a7);
    ((uint4*)(g_act1h + (size_t)n * H1DIM))[lane] = ov;
    // layer-2 logits
    float4 ws0 = __ldg((const float4*)(g_wa2s + 8 * lane));
    float4 ws1 = __ldg((const float4*)(g_wa2s + 8 * lane + 4));
    float4 wd0 = __ldg((const float4*)(g_wa2d + 8 * lane));
    float4 wd1 = __ldg((const float4*)(g_wa2d + 8 * lane + 4));
    float ps = a0 * ws0.x + a1 * ws0.y + a2 * ws0.z + a3 * ws0.w
             + a4 * ws1.x + a5 * ws1.y + a6 * ws1.z + a7 * ws1.w;
    float pd = a0 * wd0.x + a1 * wd0.y + a2 * wd0.z + a3 * wd0.w
             + a4 * wd1.x + a5 * wd1.y + a6 * wd1.z + a7 * wd1.w;
#pragma unroll
    for (int o = 16; o; o >>= 1) {
        ps += __shfl_xor_sync(0xffffffffu, ps, o);
        pd += __shfl_xor_sync(0xffffffffu, pd, o);
    }
    if (lane == 0) {
        g_as2[n] = ps;
        g_ad2[n] = pd;
    }
}

// h2 = act @ W2 (4 nodes x 4 cols / thread), fp16 stores.
#define SA_STRIDE 264
#define TILE 64
__global__ void __launch_bounds__(256) k_l2(const float* __restrict__ W2) {
    __shared__ float sA[TILE * SA_STRIDE];
    int t = threadIdx.x, lane = t & 31, w = t >> 5;
    int base = blockIdx.x * TILE;
    for (int r = w; r < TILE; r += 8) {
        int n = base + r;
        float4 o0 = {0,0,0,0}, o1 = {0,0,0,0};
        if (n < NN) {
            uint4 hv = ((const uint4*)(g_act1h + (size_t)n * H1DIM))[lane];
            float2 f0 = __half22float2(*(__half2*)&hv.x);
            float2 f1 = __half22float2(*(__half2*)&hv.y);
            float2 f2 = __half22float2(*(__half2*)&hv.z);
            float2 f3 = __half22float2(*(__half2*)&hv.w);
            o0.x = f0.x; o0.y = f0.y; o0.z = f1.x; o0.w = f1.y;
            o1.x = f2.x; o1.y = f2.y; o1.z = f3.x; o1.w = f3.y;
        }
        float4* sp = (float4*)(sA + r * SA_STRIDE + 8 * lane);
        sp[0] = o0;
        sp[1] = o1;
    }
    __syncthreads();
    int cg = t & 15;
    int ng = t >> 4;
    const float4* W2v4 = (const float4*)W2;
    float4 acc0 = {0,0,0,0}, acc1 = {0,0,0,0}, acc2 = {0,0,0,0}, acc3 = {0,0,0,0};
    const float* a0 = sA + (ng     ) * SA_STRIDE;
    const float* a1 = sA + (ng + 16) * SA_STRIDE;
    const float* a2 = sA + (ng + 32) * SA_STRIDE;
    const float* a3 = sA + (ng + 48) * SA_STRIDE;
#pragma unroll 4
    for (int k = 0; k < H1DIM; k += 4) {
        float4 v0 = *(const float4*)(a0 + k);
        float4 v1 = *(const float4*)(a1 + k);
        float4 v2 = *(const float4*)(a2 + k);
        float4 v3 = *(const float4*)(a3 + k);
        float4 w0 = __ldg(&W2v4[(k + 0) * 16 + cg]);
        float4 w1 = __ldg(&W2v4[(k + 1) * 16 + cg]);
        float4 w2 = __ldg(&W2v4[(k + 2) * 16 + cg]);
        float4 w3 = __ldg(&W2v4[(k + 3) * 16 + cg]);
#define STEP(vv, ww) \
        acc0.x = fmaf(v0.vv, ww.x, acc0.x); acc0.y = fmaf(v0.vv, ww.y, acc0.y); \
        acc0.z = fmaf(v0.vv, ww.z, acc0.z); acc0.w = fmaf(v0.vv, ww.w, acc0.w); \
        acc1.x = fmaf(v1.vv, ww.x, acc1.x); acc1.y = fmaf(v1.vv, ww.y, acc1.y); \
        acc1.z = fmaf(v1.vv, ww.z, acc1.z); acc1.w = fmaf(v1.vv, ww.w, acc1.w); \
        acc2.x = fmaf(v2.vv, ww.x, acc2.x); acc2.y = fmaf(v2.vv, ww.y, acc2.y); \
        acc2.z = fmaf(v2.vv, ww.z, acc2.z); acc2.w = fmaf(v2.vv, ww.w, acc2.w); \
        acc3.x = fmaf(v3.vv, ww.x, acc3.x); acc3.y = fmaf(v3.vv, ww.y, acc3.y); \
        acc3.z = fmaf(v3.vv, ww.z, acc3.z); acc3.w = fmaf(v3.vv, ww.w, acc3.w);
        STEP(x, w0) STEP(y, w1) STEP(z, w2) STEP(w, w3)
#undef STEP
    }
    float4 accs[4] = {acc0, acc1, acc2, acc3};
#pragma unroll
    for (int i = 0; i < 4; i++) {
        int n = base + ng + 16 * i;
        if (n < NN) {
            __half2* hp = (__half2*)(g_h2h + (size_t)n * H2DIM + 4 * cg);
            float4 v = accs[i];
            hp[0] = __floats2half2_rn(v.x, v.y);
            hp[1] = __floats2half2_rn(v.z, v.w);
        }
    }
}

// ---- layer-2 node aggregation: warp per dst node ---------------------------
__global__ void __launch_bounds__(256) k_node2() {
    int t = threadIdx.x, lane = t & 31, w = t >> 5;
    int n = blockIdx.x * 8 + w;
    if (n >= NN) return;
    float adv = g_ad2[n];
    int beg = g_ptr[n], end = g_ptr[n + 1];
    // self loop
    float wv = expf(lrelu(g_as2[n] + adv));
    float z = wv;
    unsigned hu = ((const unsigned*)(g_h2h + (size_t)n * H2DIM))[lane];
    float2 f = __half22float2(*(__half2*)&hu);
    float ax = wv * f.x, ay = wv * f.y;
    int sn = 0; unsigned hn = 0; float en = 0.f;
    if (beg < end) {
        sn = g_csr[beg];
        hn = ((const unsigned*)(g_h2h + (size_t)sn * H2DIM))[lane];
        en = g_as2[sn];
    }
    for (int j = beg; j < end; j++) {
        unsigned hc = hn; float ec = en;
        if (j + 1 < end) {
            int s2 = g_csr[j + 1];
            hn = ((const unsigned*)(g_h2h + (size_t)s2 * H2DIM))[lane];
            en = g_as2[s2];
        }
        float wj = expf(lrelu(ec + adv));
        z += wj;
        f = __half22float2(*(__half2*)&hc);
        ax = fmaf(wj, f.x, ax);
        ay = fmaf(wj, f.y, ay);
    }
    float rz = 1.f / z;
    float2 o = {ax * rz, ay * rz};
    *(float2*)(g_out2 + (size_t)n * H2DIM + 2 * lane) = o;
}

// mean over nodes (bias folded into k_out)
__global__ void k_final() {
    int t = threadIdx.x;  // 256
    int col = t & 63, ns = t >> 6;
    double sum = 0.0;
    for (int n = blockIdx.x * 4 + ns; n < NN; n += gridDim.x * 4)
        sum += (double)g_out2[(size_t)n * H2DIM + col];
    __shared__ double sd[256];
    sd[t] = sum;
    __syncthreads();
    if (t < 128) sd[t] += sd[t + 128];
    __syncthreads();
    if (t < 64) atomicAdd(&g_final[t], sd[t] + sd[t + 64]);
}

__global__ void k_out(float* __restrict__ out, const float* __restrict__ b2) {
    int t = threadIdx.x;
    if (t < H2DIM) out[t] = (float)(g_final[t] * (1.0 / (double)NN)) + b2[t];
}

// ---------------- launch -----------------------------------------------------
extern "C" void kernel_launch(void* const* d_in, const int* in_sizes, int n_in,
                              void* d_out, int out_size) {
    const float* x   = (const float*)d_in[0];
    const int*   ei  = (const int*)d_in[1];   // jax demotes int64 -> int32
    const float* W1  = (const float*)d_in[2];
    const float* as1 = (const float*)d_in[3];
    const float* ad1 = (const float*)d_in[4];
    const float* b1  = (const float*)d_in[5];
    const float* W2  = (const float*)d_in[6];
    const float* as2 = (const float*)d_in[7];
    const float* ad2 = (const float*)d_in[8];
    const float* b2  = (const float*)d_in[9];
    float* out = (float*)d_out;

    (void)in_sizes; (void)n_in; (void)out_size;

    k_pre<<<1, 256>>>(W1, as1, ad1, W2, as2, ad2);
    k_gemm1<<<(NN + G1TILE - 1) / G1TILE, 256>>>(x, W1);
    k_deg<<<(EE + 255) / 256, 256>>>(ei);
    k_scanA<<<NSCB, SCB>>>();
    k_scanB<<<1, 32>>>();
    k_scanC<<<NSCB, SCB>>>();
    k_scatter<<<(EE + 255) / 256, 256>>>(ei);
    k_node1<<<(NN + 7) / 8, 256>>>(b1);
    k_l2<<<(NN + TILE - 1) / TILE, 256>>>(W2);
    k_node2<<<(NN + 7) / 8, 256>>>();
    k_final<<<148, 256>>>();
    k_out<<<1, 64>>>(out, b2);
}